// round 13
// baseline (speedup 1.0000x reference)
#include <cuda_runtime.h>
#include <cuda_fp16.h>
#include <cstdint>

// ---------------------------------------------------------------------------
// PCQLinear: w_q = fakequant(weight, global min/max); out = x @ w_q^T + bias;
// per-cluster min/max -> EMA range update -> fakequant.
//
// GEMM: w_q = s*(q-z), (q-z) integer in [-127,128] -> EXACT in f16.
// x = xh + xl, both f16 (residual ~2^-22). out = s*(xh@Qc^T + xl@Qc^T) + bias.
// hi pass: mma m16n8k16 f32.f16.f16.f32 ; lo pass: f16.f16.f16.f16 (f16 acc,
// safe: lo partials ~0.6 << f16 range, rounding ~1e-5 abs vs quant step 0.39).
// R13: tests whether f16-acc HMMA is double-rate vs f32-acc on sm_103.
// ---------------------------------------------------------------------------

#define FLT_BIG 3.402823466e38f

#define BM 128
#define BN 128
#define BKB 32                 // k per chunk (f16 elems) = 64B rows
#define NTH 256
#define STG_B 24576            // AH 8K | AL 8K | B 8K
#define OFF_AL 8192
#define OFF_B  16384
#define NSTG 4
#define SMEM_BYTES (NSTG * STG_B)   // 96 KB (x2 CTAs = 192 KB)

// Scratch (allocation-free: __device__ globals)
__device__ __half g_wqc[4096l * 4096];    // (q - z), exact ints in f16
__device__ __half g_xh[10240l * 4096];
__device__ __half g_xl[10240l * 4096];
__device__ unsigned g_wmin_u, g_wmax_u;
__device__ float g_sw, g_zw;
__device__ unsigned g_cmin[64], g_cmax[64];
__device__ float g_s3[64], g_z3[64];

// ---------------------------------------------------------------------------
__device__ __forceinline__ unsigned f2ord(float f) {
    unsigned u = __float_as_uint(f);
    return (u & 0x80000000u) ? ~u : (u | 0x80000000u);
}
__device__ __forceinline__ float ord2f(unsigned u) {
    return __uint_as_float((u & 0x80000000u) ? (u & 0x7FFFFFFFu) : ~u);
}
__device__ __forceinline__ uint32_t smem_u32(const void* p) {
    uint32_t a;
    asm("{ .reg .u64 t; cvta.to.shared.u64 t, %1; cvt.u32.u64 %0, t; }"
        : "=r"(a) : "l"(p));
    return a;
}
__device__ __forceinline__ void cp16(uint32_t dst, const void* src) {
    asm volatile("cp.async.cg.shared.global [%0], [%1], 16;"
                 :: "r"(dst), "l"(src) : "memory");
}
__device__ __forceinline__ void cp_commit() {
    asm volatile("cp.async.commit_group;" ::: "memory");
}
template <int N>
__device__ __forceinline__ void cp_wait() {
    asm volatile("cp.async.wait_group %0;" :: "n"(N) : "memory");
}
__device__ __forceinline__ void ldsm4(uint32_t* r, uint32_t addr) {
    asm volatile("ldmatrix.sync.aligned.m8n8.x4.shared.b16 {%0,%1,%2,%3}, [%4];"
                 : "=r"(r[0]), "=r"(r[1]), "=r"(r[2]), "=r"(r[3]) : "r"(addr));
}
// hi pass: f16 inputs, f32 accum
__device__ __forceinline__ void mma_hi(float* d, const uint32_t* a,
                                       uint32_t b0, uint32_t b1) {
    asm("mma.sync.aligned.m16n8k16.row.col.f32.f16.f16.f32 "
        "{%0,%1,%2,%3}, {%4,%5,%6,%7}, {%8,%9}, {%0,%1,%2,%3};"
        : "+f"(d[0]), "+f"(d[1]), "+f"(d[2]), "+f"(d[3])
        : "r"(a[0]), "r"(a[1]), "r"(a[2]), "r"(a[3]), "r"(b0), "r"(b1));
}
// lo pass: f16 inputs, f16 accum (packed f16x2 pair)
__device__ __forceinline__ void mma_lo(uint32_t* d, const uint32_t* a,
                                       uint32_t b0, uint32_t b1) {
    asm("mma.sync.aligned.m16n8k16.row.col.f16.f16.f16.f16 "
        "{%0,%1}, {%2,%3,%4,%5}, {%6,%7}, {%0,%1};"
        : "+r"(d[0]), "+r"(d[1])
        : "r"(a[0]), "r"(a[1]), "r"(a[2]), "r"(a[3]), "r"(b0), "r"(b1));
}

// ---------------------------------------------------------------------------
__global__ void init_scratch_kernel() {
    int t = threadIdx.x;
    if (t == 0) { g_wmin_u = 0xFFFFFFFFu; g_wmax_u = 0u; }
    if (t < 64) { g_cmin[t] = 0xFFFFFFFFu; g_cmax[t] = 0u; }
}

// ---------------------------------------------------------------------------
__global__ void wminmax_kernel(const float* __restrict__ w, long n4) {
    float mn = FLT_BIG, mx = -FLT_BIG;
    long stride = (long)gridDim.x * blockDim.x;
    for (long i = (long)blockIdx.x * blockDim.x + threadIdx.x; i < n4; i += stride) {
        float4 v = ((const float4*)w)[i];
        mn = fminf(mn, fminf(fminf(v.x, v.y), fminf(v.z, v.w)));
        mx = fmaxf(mx, fmaxf(fmaxf(v.x, v.y), fmaxf(v.z, v.w)));
    }
    #pragma unroll
    for (int o = 16; o; o >>= 1) {
        mn = fminf(mn, __shfl_down_sync(0xFFFFFFFFu, mn, o));
        mx = fmaxf(mx, __shfl_down_sync(0xFFFFFFFFu, mx, o));
    }
    __shared__ float smn[8], smx[8];
    int lane = threadIdx.x & 31, wrp = threadIdx.x >> 5;
    if (!lane) { smn[wrp] = mn; smx[wrp] = mx; }
    __syncthreads();
    if (threadIdx.x == 0) {
        for (int i = 1; i < (int)(blockDim.x >> 5); i++) {
            mn = fminf(mn, smn[i]); mx = fmaxf(mx, smx[i]);
        }
        atomicMin(&g_wmin_u, f2ord(mn));
        atomicMax(&g_wmax_u, f2ord(mx));
    }
}

__global__ void wparams_kernel() {
    float mn = ord2f(g_wmin_u), mx = ord2f(g_wmax_u);
    float s = __fdiv_rn(mx - mn, 255.0f);
    g_sw = s;
    g_zw = -rintf(__fdiv_rn(mn, s));
}

// quantize weights to centered integer codes Qc = clip(round(w/s+z),0,255)-z,
// stored exactly as f16 (|Qc| <= 255, integers exact in f16).
__global__ void wquant_kernel(const float* __restrict__ w, long n4) {
    float s = g_sw, zp = g_zw;
    long stride = (long)gridDim.x * blockDim.x;
    for (long i = (long)blockIdx.x * blockDim.x + threadIdx.x; i < n4; i += stride) {
        float4 v = ((const float4*)w)[i];
        float q0 = fminf(fmaxf(rintf(__fdiv_rn(v.x, s) + zp), 0.0f), 255.0f) - zp;
        float q1 = fminf(fmaxf(rintf(__fdiv_rn(v.y, s) + zp), 0.0f), 255.0f) - zp;
        float q2 = fminf(fmaxf(rintf(__fdiv_rn(v.z, s) + zp), 0.0f), 255.0f) - zp;
        float q3 = fminf(fmaxf(rintf(__fdiv_rn(v.w, s) + zp), 0.0f), 255.0f) - zp;
        __half2* o = (__half2*)g_wqc + i * 2;
        o[0] = __halves2half2(__float2half_rn(q0), __float2half_rn(q1));
        o[1] = __halves2half2(__float2half_rn(q2), __float2half_rn(q3));
    }
}

// split x into f16 hi + lo (residual ~2^-22 * |x|)
__global__ void xsplit_kernel(const float* __restrict__ x, long n4) {
    long stride = (long)gridDim.x * blockDim.x;
    for (long i = (long)blockIdx.x * blockDim.x + threadIdx.x; i < n4; i += stride) {
        float4 v = ((const float4*)x)[i];
        __half h0 = __float2half_rn(v.x);
        __half h1 = __float2half_rn(v.y);
        __half h2 = __float2half_rn(v.z);
        __half h3 = __float2half_rn(v.w);
        __half2* oh = (__half2*)g_xh + i * 2;
        oh[0] = __halves2half2(h0, h1);
        oh[1] = __halves2half2(h2, h3);
        __half2* ol = (__half2*)g_xl + i * 2;
        ol[0] = __halves2half2(__float2half_rn(v.x - __half2float(h0)),
                               __float2half_rn(v.y - __half2float(h1)));
        ol[1] = __halves2half2(__float2half_rn(v.z - __half2float(h2)),
                               __float2half_rn(v.w - __half2float(h3)));
    }
}

// ---------------------------------------------------------------------------
// f16 2-pass GEMM: out = s*( xh@Qc^T (f32 acc) + xl@Qc^T (f16 acc) ) + bias.
// CTA 128x128, BK=32 f16 (64B rows), 4-stage cp.async ring, one sync/chunk.
// smem swizzle: chunk' = chunk ^ ((row>>1)&3) -> conflict-free ldmatrix mats.
// ---------------------------------------------------------------------------
__global__ __launch_bounds__(NTH, 2)
void gemm_f16_kernel(const float* __restrict__ bias, float* __restrict__ out,
                     int IND, int ND, int nPerCluster) {
    extern __shared__ char smc[];
    const int tid = threadIdx.x;
    const int lane = tid & 31, wid = tid >> 5;
    const int q = lane & 3, r4 = lane >> 2;
    const int wm = wid & 3, wn = wid >> 2;   // 4x2 warp grid, warp 32x64
    const int Rw = wm * 32, Cw = wn * 64;
    const int m0 = blockIdx.y * BM;
    const int n0 = blockIdx.x * BN;
    const uint32_t sb = smem_u32(smc);

    float acc[2][8][4];          // hi pass, f32
    uint32_t accl[2][8][2];      // lo pass, packed f16x2 pairs
    #pragma unroll
    for (int mi = 0; mi < 2; mi++)
        #pragma unroll
        for (int nb = 0; nb < 8; nb++) {
            #pragma unroll
            for (int e = 0; e < 4; e++) acc[mi][nb][e] = 0.0f;
            accl[mi][nb][0] = 0u; accl[mi][nb][1] = 0u;
        }

    // cp.async issue: 512 16B chunks per tensor, 2 per thread per tensor
    auto issue = [&](int ck, int s) {
        const uint32_t st = sb + s * STG_B;
        const long kk = (long)ck * BKB;
        #pragma unroll
        for (int i = 0; i < 2; i++) {
            int c = tid + i * 256;
            int r = c >> 2, g = c & 3;
            uint32_t d = (uint32_t)(r * 64 + ((g ^ ((r >> 1) & 3)) << 4));
            long goff = kk + g * 8;
            cp16(st + d,          g_xh  + (size_t)(m0 + r) * IND + goff);
            cp16(st + OFF_AL + d, g_xl  + (size_t)(m0 + r) * IND + goff);
            cp16(st + OFF_B + d,  g_wqc + (size_t)(n0 + r) * IND + goff);
        }
    };

    // ldmatrix lane bases (identical to validated R8/R12 kernel)
    const int arow_base = (lane & 7) + ((lane >> 3) & 1) * 8;
    const int ag = lane >> 4;
    const int brow_base = lane & 7;
    const int bg = lane >> 3;

    auto compute = [&](int s) {
        const uint32_t st = sb + s * STG_B;
        uint32_t ah[2][2][4], al[2][2][4];
        #pragma unroll
        for (int mi = 0; mi < 2; mi++)
            #pragma unroll
            for (int at = 0; at < 2; at++) {
                int r = Rw + mi * 16 + arow_base;
                int g = at * 2 + ag;
                uint32_t off = (uint32_t)(r * 64 + ((g ^ ((r >> 1) & 3)) << 4));
                ldsm4(ah[mi][at], st + off);
                ldsm4(al[mi][at], st + OFF_AL + off);
            }
        #pragma unroll
        for (int nb = 0; nb < 8; nb++) {
            int r = Cw + nb * 8 + brow_base;
            uint32_t off = (uint32_t)(r * 64 + ((bg ^ ((r >> 1) & 3)) << 4));
            uint32_t b[4];
            ldsm4(b, st + OFF_B + off);
            #pragma unroll
            for (int mi = 0; mi < 2; mi++) {
                mma_hi(acc[mi][nb],  ah[mi][0], b[0], b[1]);
                mma_lo(accl[mi][nb], al[mi][0], b[0], b[1]);
                mma_hi(acc[mi][nb],  ah[mi][1], b[2], b[3]);
                mma_lo(accl[mi][nb], al[mi][1], b[2], b[3]);
            }
        }
    };

    const int NCH = IND / BKB;   // 128

    // prologue: 3 chunks in flight
    issue(0, 0); cp_commit();
    issue(1, 1); cp_commit();
    issue(2, 2); cp_commit();

    for (int k = 0; k < NCH; k++) {
        cp_wait<2>();
        __syncthreads();
        if (k + 3 < NCH) issue(k + 3, (k + 3) & (NSTG - 1));
        cp_commit();   // commit every iter (possibly empty) to keep counts
        compute(k & (NSTG - 1));
    }

    // epilogue: combine hi+lo, scale by s, +bias, per-cluster min/max, store
    const float sf = g_sw;
    float lmin = FLT_BIG, lmax = -FLT_BIG;
    float2 bz[8];
    #pragma unroll
    for (int nb = 0; nb < 8; nb++)
        bz[nb] = *(const float2*)(bias + n0 + Cw + nb * 8 + 2 * q);

    #pragma unroll
    for (int mi = 0; mi < 2; mi++) {
        int r0 = m0 + Rw + mi * 16 + r4;
        #pragma unroll
        for (int nb = 0; nb < 8; nb++) {
            int col = n0 + Cw + nb * 8 + 2 * q;
            float2 lo01 = __half22float2(*(__half2*)&accl[mi][nb][0]);
            float2 lo23 = __half22float2(*(__half2*)&accl[mi][nb][1]);
            float v0 = sf * (acc[mi][nb][0] + lo01.x) + bz[nb].x;
            float v1 = sf * (acc[mi][nb][1] + lo01.y) + bz[nb].y;
            float v2 = sf * (acc[mi][nb][2] + lo23.x) + bz[nb].x;
            float v3 = sf * (acc[mi][nb][3] + lo23.y) + bz[nb].y;
            lmin = fminf(lmin, fminf(fminf(v0, v1), fminf(v2, v3)));
            lmax = fmaxf(lmax, fmaxf(fmaxf(v0, v1), fmaxf(v2, v3)));
            *(float2*)(out + (size_t)r0 * ND + col)       = make_float2(v0, v1);
            *(float2*)(out + (size_t)(r0 + 8) * ND + col) = make_float2(v2, v3);
        }
    }

    #pragma unroll
    for (int o = 16; o; o >>= 1) {
        lmin = fminf(lmin, __shfl_down_sync(0xFFFFFFFFu, lmin, o));
        lmax = fmaxf(lmax, __shfl_down_sync(0xFFFFFFFFu, lmax, o));
    }
    __shared__ float smn[8], smx[8];
    if (!lane) { smn[wid] = lmin; smx[wid] = lmax; }
    __syncthreads();
    if (tid == 0) {
        float mn = smn[0], mx = smx[0];
        #pragma unroll
        for (int i = 1; i < 8; i++) { mn = fminf(mn, smn[i]); mx = fmaxf(mx, smx[i]); }
        int cl = m0 / nPerCluster;
        atomicMin(&g_cmin[cl], f2ord(mn));
        atomicMax(&g_cmax[cl], f2ord(mx));
    }
}

// ---------------------------------------------------------------------------
__global__ void range_kernel(const float* __restrict__ act_range,
                             const int* __restrict__ cinfo,
                             float* __restrict__ rout, int Kc) {
    int t = threadIdx.x;
    if (t < 2 * Kc) rout[t] = act_range[t];
    __syncthreads();
    if (t < Kc) {
        int c = cinfo[2 * t];
        float mn = ord2f(g_cmin[t]);
        float mx = ord2f(g_cmax[t]);
        float om = act_range[2 * c], oM = act_range[2 * c + 1];
        const float SM  = 0.999f;
        const float OMS = (float)(1.0 - 0.999);
        float nm = om * SM + mn * OMS;
        float nM = oM * SM + mx * OMS;
        rout[2 * c]     = nm;
        rout[2 * c + 1] = nM;
        float s = __fdiv_rn(nM - nm, 255.0f);
        g_s3[t] = s;
        g_z3[t] = -rintf(__fdiv_rn(nm, s));
    }
}

// ---------------------------------------------------------------------------
// 2-D grid: blockIdx.y = row, blockIdx.x tiles columns (no per-elem division)
__global__ void quant_out_kernel(float* __restrict__ out, int nd4,
                                 int nPerCluster) {
    int row = blockIdx.y;
    int g = row / nPerCluster;
    float s = g_s3[g], zp = g_z3[g];
    float4* rowp = (float4*)out + (size_t)row * nd4;
    for (int i = blockIdx.x * blockDim.x + threadIdx.x; i < nd4;
         i += gridDim.x * blockDim.x) {
        float4 v = rowp[i];
        v.x = (fminf(fmaxf(rintf(__fdiv_rn(v.x, s) + zp), 0.0f), 255.0f) - zp) * s;
        v.y = (fminf(fmaxf(rintf(__fdiv_rn(v.y, s) + zp), 0.0f), 255.0f) - zp) * s;
        v.z = (fminf(fmaxf(rintf(__fdiv_rn(v.z, s) + zp), 0.0f), 255.0f) - zp) * s;
        v.w = (fminf(fmaxf(rintf(__fdiv_rn(v.w, s) + zp), 0.0f), 255.0f) - zp) * s;
        rowp[i] = v;
    }
}

// ---------------------------------------------------------------------------
extern "C" void kernel_launch(void* const* d_in, const int* in_sizes, int n_in,
                              void* d_out, int out_size) {
    const float* x         = (const float*)d_in[0];
    const float* weight    = (const float*)d_in[1];
    const float* bias      = (const float*)d_in[2];
    const float* act_range = (const float*)d_in[3];
    const int*   cinfo     = (const int*)d_in[4];

    int OUT = in_sizes[2];             // bias length
    int IN  = in_sizes[1] / OUT;       // weight is [OUT, IN]
    int B   = in_sizes[0] / IN;        // x is [B, IN]
    int Kc  = in_sizes[3] / 2;         // act_range [K, 2]
    int nPer = B / Kc;

    float* out  = (float*)d_out;
    float* rout = out + (size_t)B * OUT;

    long w4 = (long)OUT * IN / 4;
    long x4 = (long)B * IN / 4;

    init_scratch_kernel<<<1, 64>>>();
    wminmax_kernel<<<1024, 256>>>(weight, w4);
    wparams_kernel<<<1, 1>>>();
    wquant_kernel<<<2048, 256>>>(weight, w4);
    xsplit_kernel<<<4096, 256>>>(x, x4);

    cudaFuncSetAttribute(gemm_f16_kernel,
                         cudaFuncAttributeMaxDynamicSharedMemorySize, SMEM_BYTES);
    dim3 grid(OUT / BN, B / BM);
    gemm_f16_kernel<<<grid, NTH, SMEM_BYTES>>>(bias, out, IN, OUT, nPer);

    range_kernel<<<1, 128>>>(act_range, cinfo, rout, Kc);
    dim3 qgrid(2, B);
    quant_out_kernel<<<qgrid, 256>>>(out, OUT / 4, nPer);
}